// round 11
// baseline (speedup 1.0000x reference)
#include <cuda_runtime.h>
#include <math.h>

#define Hn   2048
#define SEQ  2048
#define NBLK 148
#define TPB  288     // 8 worker warps (256) + 1 poller warp
#define WTH  256
#define MAXR 14      // max rows per block: ceil(2048/148)

// ------------------------------------------------------------------
// Static device scratch (no cudaMalloc allowed)
// ------------------------------------------------------------------
__device__ float d_XF[SEQ * Hn];   // x @ Wfx^T + bfx
__device__ float d_XH[SEQ * Hn];   // x @ Whx^T + bhx
__device__ float d_hbuf[Hn];       // hidden state (cross-block)
__device__ float d_gbuf[Hn];       // f * h (cross-block)
__device__ unsigned d_count = 0;   // arrival counter: WRITERS ONLY (REDs)
__device__ unsigned d_epoch = 0;   // broadcast line: 1 writer (block 0 poller)
__device__ unsigned d_base  = 0;   // counter value at start of this run

__device__ __forceinline__ void red_arrive(unsigned* p) {
    asm volatile("red.release.gpu.global.add.u32 [%0], %1;"
                 :: "l"(p), "r"(1u) : "memory");
}
__device__ __forceinline__ unsigned ld_acq(const unsigned* p) {
    unsigned v;
    asm volatile("ld.acquire.gpu.global.u32 %0, [%1];" : "=r"(v) : "l"(p) : "memory");
    return v;
}
__device__ __forceinline__ void st_rel(unsigned* p, unsigned v) {
    asm volatile("st.release.gpu.global.u32 [%0], %1;" :: "l"(p), "r"(v) : "memory");
}
// workers-only barrier
__device__ __forceinline__ void bar1() {
    asm volatile("bar.sync 1, %0;" :: "n"(WTH) : "memory");
}
// workers + poller barrier
__device__ __forceinline__ void bar2() {
    asm volatile("bar.sync 2, %0;" :: "n"(TPB) : "memory");
}

// ------------------------------------------------------------------
// Precompute GEMM:  C[s][n] = sum_k x[s][k] * W[n][k] + bias[n]
// ------------------------------------------------------------------
__global__ __launch_bounds__(256, 2) void mgu_gemm(
    const float* __restrict__ x,
    const float* __restrict__ Wfx, const float* __restrict__ bfx,
    const float* __restrict__ Whx, const float* __restrict__ bhx)
{
    const float* __restrict__ W    = (blockIdx.z == 0) ? Wfx : Whx;
    const float* __restrict__ bias = (blockIdx.z == 0) ? bfx : bhx;
    float* __restrict__ C          = (blockIdx.z == 0) ? d_XF : d_XH;

    __shared__ float As[16][132];
    __shared__ float Bs[16][132];

    const int bm  = blockIdx.y * 128;
    const int bn  = blockIdx.x * 128;
    const int tid = threadIdx.x;
    const int tr  = (tid >> 4) << 3;
    const int tc  = (tid & 15) << 3;

    float acc[8][8];
#pragma unroll
    for (int i = 0; i < 8; i++)
#pragma unroll
        for (int j = 0; j < 8; j++) acc[i][j] = 0.f;

    for (int k0 = 0; k0 < 2048; k0 += 16) {
#pragma unroll
        for (int i = 0; i < 2; i++) {
            int q   = tid + (i << 8);
            int row = q >> 2;
            int kq  = (q & 3) << 2;
            float4 va = *(const float4 *)(x + (size_t)(bm + row) * 2048 + k0 + kq);
            As[kq + 0][row] = va.x; As[kq + 1][row] = va.y;
            As[kq + 2][row] = va.z; As[kq + 3][row] = va.w;
            float4 vb = *(const float4 *)(W + (size_t)(bn + row) * 2048 + k0 + kq);
            Bs[kq + 0][row] = vb.x; Bs[kq + 1][row] = vb.y;
            Bs[kq + 2][row] = vb.z; Bs[kq + 3][row] = vb.w;
        }
        __syncthreads();
#pragma unroll
        for (int k = 0; k < 16; k++) {
            float a[8], bvv[8];
            *(float4 *)(a)     = *(const float4 *)&As[k][tr];
            *(float4 *)(a + 4) = *(const float4 *)&As[k][tr + 4];
            *(float4 *)(bvv)     = *(const float4 *)&Bs[k][tc];
            *(float4 *)(bvv + 4) = *(const float4 *)&Bs[k][tc + 4];
#pragma unroll
            for (int i = 0; i < 8; i++)
#pragma unroll
                for (int j = 0; j < 8; j++) acc[i][j] += a[i] * bvv[j];
        }
        __syncthreads();
    }

    float bj[8];
#pragma unroll
    for (int j = 0; j < 8; j++) bj[j] = __ldg(&bias[bn + tc + j]);
#pragma unroll
    for (int i = 0; i < 8; i++) {
        float4 v0 = make_float4(acc[i][0] + bj[0], acc[i][1] + bj[1],
                                acc[i][2] + bj[2], acc[i][3] + bj[3]);
        float4 v1 = make_float4(acc[i][4] + bj[4], acc[i][5] + bj[5],
                                acc[i][6] + bj[6], acc[i][7] + bj[7]);
        size_t off = (size_t)(bm + tr + i) * 2048 + bn + tc;
        *(float4 *)(C + off)     = v0;
        *(float4 *)(C + off + 4) = v1;
    }
}

// ------------------------------------------------------------------
// Persistent scan. 148 blocks (1/SM). Warps 0-7 = workers, warp 8 =
// poller. Sync substrate: arrival REDs go to d_count (no readers
// but ONE aggregator -> fast serialization); block 0's poller is the
// single reader of d_count and broadcasts the reached target via
// d_epoch; the other 147 pollers read d_epoch (read-shared line,
// single writer -> no ownership ping-pong).
// ------------------------------------------------------------------
__global__ __launch_bounds__(TPB, 1) void mgu_scan(
    const float* __restrict__ h0,
    const float* __restrict__ Wfh, const float* __restrict__ bfh,
    const float* __restrict__ Whf, const float* __restrict__ bhf,
    float* __restrict__ out)
{
    extern __shared__ float sW[];
    __shared__ float sPart[MAXR][8];
    __shared__ float sF[MAXR];
    __shared__ float sHold[MAXR];
    __shared__ float sBfh[MAXR];
    __shared__ float sBhf[MAXR];
    __shared__ unsigned sBase;

    const int b   = blockIdx.x;
    const int tid = threadIdx.x;
    const int r0  = (b * Hn) / NBLK;
    const int r1  = ((b + 1) * Hn) / NBLK;
    const int nr  = r1 - r0;               // 13 or 14

    float* sWf = sW;                        // Wfh rows
    float* sWh = sW + nr * Hn;              // Whf rows

    if (tid == 0) sBase = *(volatile unsigned *)&d_base;

    {   // stage weight rows into SMEM (coalesced float4)
        const float4* gf = (const float4 *)(Wfh + (size_t)r0 * Hn);
        const float4* gh = (const float4 *)(Whf + (size_t)r0 * Hn);
        float4* sf4 = (float4 *)sWf;
        float4* sh4 = (float4 *)sWh;
        const int n4 = nr * (Hn / 4);
        for (int i = tid; i < n4; i += TPB) { sf4[i] = gf[i]; sh4[i] = gh[i]; }
    }
    if (tid < nr) {
        sBfh[tid]  = bfh[r0 + tid];
        sBhf[tid]  = bhf[r0 + tid];
        sHold[tid] = h0[r0 + tid];
    }
    for (int i = b * TPB + tid; i < Hn; i += NBLK * TPB) d_hbuf[i] = h0[i];

    __syncthreads();
    const unsigned base = sBase;
    if (tid == 0) red_arrive(&d_count);      // gen 1: weights + h0 published

    // ---------------- poller warp ----------------
    if (tid >= WTH) {
        if (b == 0) {
            // aggregator: sole reader of d_count, sole writer of d_epoch
            for (unsigned g = 1; g <= 2u * SEQ; g++) {
                if (tid == WTH) {
                    unsigned target = base + g * (unsigned)NBLK;
                    while ((int)(ld_acq(&d_count) - target) < 0) { }
                    st_rel(&d_epoch, target);
                }
                bar2();
            }
            if (tid == WTH)
                *(volatile unsigned *)&d_base = base + 2u * SEQ * (unsigned)NBLK;
        } else {
            for (unsigned g = 1; g <= 2u * SEQ; g++) {
                if (tid == WTH) {
                    unsigned target = base + g * (unsigned)NBLK;
                    while ((int)(ld_acq(&d_epoch) - target) < 0) { }
                }
                bar2();
            }
        }
        return;
    }

    // ---------------- workers ----------------
    const int lane = tid & 31;
    const int wid  = tid >> 5;
    const int cA   = wid * 128 + lane * 4;          // conflict-free chunk 0
    const int cB   = 1024 + wid * 128 + lane * 4;   // conflict-free chunk 1

    float xf_c = 0.f, xh_c = 0.f;
    if (tid < nr) {
        xf_c = __ldg(&d_XF[r0 + tid]);
        xh_c = __ldg(&d_XH[r0 + tid]);
    }

    float4 wr[MAXR][2];
#pragma unroll
    for (int r = 0; r < MAXR; r++) {                // preload Wfh for t=0
        wr[r][0] = *(const float4 *)(sWf + r * Hn + cA);
        wr[r][1] = *(const float4 *)(sWf + r * Hn + cB);
    }
    bar2();                                          // gen 1 synced: h ready

    for (int t = 0; t < SEQ; t++) {
        // ===== phase A : f = sigmoid(xf + Wfh h + bfh);  g = f*h =====
        float4 hv0 = __ldcg((const float4 *)&d_hbuf[cA]);
        float4 hv1 = __ldcg((const float4 *)&d_hbuf[cB]);

        float acc[MAXR];
#pragma unroll
        for (int r = 0; r < MAXR; r++) {
            acc[r] = wr[r][0].x * hv0.x + wr[r][0].y * hv0.y
                   + wr[r][0].z * hv0.z + wr[r][0].w * hv0.w
                   + wr[r][1].x * hv1.x + wr[r][1].y * hv1.y
                   + wr[r][1].z * hv1.z + wr[r][1].w * hv1.w;
        }
        // paired butterfly reduction: 6 SHFL per 2 rows
#pragma unroll
        for (int p = 0; p < 7; p++) {
            float a = acc[2 * p], c = acc[2 * p + 1];
            a += __shfl_xor_sync(0xffffffffu, a, 16);
            c += __shfl_xor_sync(0xffffffffu, c, 16);
            float m = (lane < 16) ? a : c;
            m += __shfl_xor_sync(0xffffffffu, m, 8);
            m += __shfl_xor_sync(0xffffffffu, m, 4);
            m += __shfl_xor_sync(0xffffffffu, m, 2);
            m += __shfl_xor_sync(0xffffffffu, m, 1);
            if (lane == 0)       sPart[2 * p][wid]     = m;
            else if (lane == 16) sPart[2 * p + 1][wid] = m;
        }
        bar1();
        if (tid < nr) {
            float4 p0 = *(const float4 *)&sPart[tid][0];
            float4 p1 = *(const float4 *)&sPart[tid][4];
            float s = (p0.x + p0.y) + (p0.z + p0.w)
                    + (p1.x + p1.y) + (p1.z + p1.w);
            float z = s + sBfh[tid] + xf_c;
            float f = 1.f / (1.f + __expf(-z));
            sF[tid] = f;
            __stcg(&d_gbuf[r0 + tid], f * sHold[tid]);
        }
        bar1();
        if (tid == 0) red_arrive(&d_count);          // gen 2t+2
#pragma unroll
        for (int r = 0; r < MAXR; r++) {             // preload Whf (hidden under sync)
            wr[r][0] = *(const float4 *)(sWh + r * Hn + cA);
            wr[r][1] = *(const float4 *)(sWh + r * Hn + cB);
        }
        bar2();                                      // gen 2t+2 synced: g ready

        // ===== phase B : h_hat = tanh(Whf g + bhf + xh); update =====
        float4 gv0 = __ldcg((const float4 *)&d_gbuf[cA]);
        float4 gv1 = __ldcg((const float4 *)&d_gbuf[cB]);

        float xf_n = 0.f, xh_n = 0.f;                // prefetch next x-projections
        if (tid < nr && t + 1 < SEQ) {
            xf_n = __ldg(&d_XF[(size_t)(t + 1) * Hn + r0 + tid]);
            xh_n = __ldg(&d_XH[(size_t)(t + 1) * Hn + r0 + tid]);
        }

#pragma unroll
        for (int r = 0; r < MAXR; r++) {
            acc[r] = wr[r][0].x * gv0.x + wr[r][0].y * gv0.y
                   + wr[r][0].z * gv0.z + wr[r][0].w * gv0.w
                   + wr[r][1].x * gv1.x + wr[r][1].y * gv1.y
                   + wr[r][1].z * gv1.z + wr[r][1].w * gv1.w;
        }
#pragma unroll
        for (int p = 0; p < 7; p++) {
            float a = acc[2 * p], c = acc[2 * p + 1];
            a += __shfl_xor_sync(0xffffffffu, a, 16);
            c += __shfl_xor_sync(0xffffffffu, c, 16);
            float m = (lane < 16) ? a : c;
            m += __shfl_xor_sync(0xffffffffu, m, 8);
            m += __shfl_xor_sync(0xffffffffu, m, 4);
            m += __shfl_xor_sync(0xffffffffu, m, 2);
            m += __shfl_xor_sync(0xffffffffu, m, 1);
            if (lane == 0)       sPart[2 * p][wid]     = m;
            else if (lane == 16) sPart[2 * p + 1][wid] = m;
        }
        bar1();
        if (tid < nr) {
            float4 p0 = *(const float4 *)&sPart[tid][0];
            float4 p1 = *(const float4 *)&sPart[tid][4];
            float s = (p0.x + p0.y) + (p0.z + p0.w)
                    + (p1.x + p1.y) + (p1.z + p1.w);
            float z  = s + sBhf[tid] + xh_c;
            float e2 = __expf(2.f * z);
            float hh = 1.f - 2.f / (e2 + 1.f);      // tanh(z)
            float f  = sF[tid];
            float ho = sHold[tid];
            float hn = ho + f * (hh - ho);          // (1-f)*h + f*h_hat
            sHold[tid] = hn;
            int row = r0 + tid;
            out[(size_t)t * Hn + row] = hn;
            __stcg(&d_hbuf[row], hn);
            if (t == SEQ - 1) out[(size_t)SEQ * Hn + row] = hn;  // h_final
        }
        bar1();
        if (t < SEQ - 1) {
            if (tid == 0) red_arrive(&d_count);      // gen 2t+3
#pragma unroll
            for (int r = 0; r < MAXR; r++) {         // preload Wfh for next step
                wr[r][0] = *(const float4 *)(sWf + r * Hn + cA);
                wr[r][1] = *(const float4 *)(sWf + r * Hn + cB);
            }
            bar2();                                  // gen 2t+3 synced: h ready
        }
        xf_c = xf_n;
        xh_c = xh_n;
    }
}

// ------------------------------------------------------------------
extern "C" void kernel_launch(void* const* d_in, const int* in_sizes, int n_in,
                              void* d_out, int out_size)
{
    const float* x   = (const float *)d_in[0];
    const float* h0  = (const float *)d_in[1];
    const float* Wfx = (const float *)d_in[2];
    const float* bfx = (const float *)d_in[3];
    const float* Wfh = (const float *)d_in[4];
    const float* bfh = (const float *)d_in[5];
    const float* Whf = (const float *)d_in[6];
    const float* bhf = (const float *)d_in[7];
    const float* Whx = (const float *)d_in[8];
    const float* bhx = (const float *)d_in[9];
    float* out = (float *)d_out;

    (void)in_sizes; (void)n_in; (void)out_size;

    const size_t smem = (size_t)MAXR * Hn * 2 * sizeof(float);  // 229376 B
    cudaFuncSetAttribute(mgu_scan, cudaFuncAttributeMaxDynamicSharedMemorySize,
                         (int)smem);

    mgu_gemm<<<dim3(16, 16, 2), 256>>>(x, Wfx, bfx, Whx, bhx);
    mgu_scan<<<NBLK, TPB, smem>>>(h0, Wfh, bfh, Whf, bhf, out);
}

// round 13
// speedup vs baseline: 1.6699x; 1.6699x over previous
#include <cuda_runtime.h>
#include <math.h>

#define Hn   2048
#define SEQ  2048
#define NBLK 148
#define TPB  288     // 8 worker warps (256) + 1 poller warp
#define WTH  256
#define MAXR 14      // max rows per block: ceil(2048/148)

// ------------------------------------------------------------------
// Static device scratch (no cudaMalloc allowed)
// ------------------------------------------------------------------
__device__ float d_XF[SEQ * Hn];   // x @ Wfx^T + bfx
__device__ float d_XH[SEQ * Hn];   // x @ Whx^T + bhx
__device__ float d_hbuf[Hn];       // hidden state (cross-block)
__device__ float d_gbuf[Hn];       // f * h (cross-block)
__device__ unsigned d_count = 0;   // monotonic barrier arrival counter
__device__ unsigned d_base  = 0;   // counter value at start of this run

__device__ __forceinline__ void red_arrive(unsigned* p) {
    asm volatile("red.release.gpu.global.add.u32 [%0], %1;"
                 :: "l"(p), "r"(1u) : "memory");
}
__device__ __forceinline__ unsigned ld_acq(const unsigned* p) {
    unsigned v;
    asm volatile("ld.acquire.gpu.global.u32 %0, [%1];" : "=r"(v) : "l"(p) : "memory");
    return v;
}
// workers-only barrier
__device__ __forceinline__ void bar1() {
    asm volatile("bar.sync 1, %0;" :: "n"(WTH) : "memory");
}
// workers + poller barrier
__device__ __forceinline__ void bar2() {
    asm volatile("bar.sync 2, %0;" :: "n"(TPB) : "memory");
}

// ------------------------------------------------------------------
// Precompute GEMM:  C[s][n] = sum_k x[s][k] * W[n][k] + bias[n]
// ------------------------------------------------------------------
__global__ __launch_bounds__(256, 2) void mgu_gemm(
    const float* __restrict__ x,
    const float* __restrict__ Wfx, const float* __restrict__ bfx,
    const float* __restrict__ Whx, const float* __restrict__ bhx)
{
    const float* __restrict__ W    = (blockIdx.z == 0) ? Wfx : Whx;
    const float* __restrict__ bias = (blockIdx.z == 0) ? bfx : bhx;
    float* __restrict__ C          = (blockIdx.z == 0) ? d_XF : d_XH;

    __shared__ float As[16][132];
    __shared__ float Bs[16][132];

    const int bm  = blockIdx.y * 128;
    const int bn  = blockIdx.x * 128;
    const int tid = threadIdx.x;
    const int tr  = (tid >> 4) << 3;
    const int tc  = (tid & 15) << 3;

    float acc[8][8];
#pragma unroll
    for (int i = 0; i < 8; i++)
#pragma unroll
        for (int j = 0; j < 8; j++) acc[i][j] = 0.f;

    for (int k0 = 0; k0 < 2048; k0 += 16) {
#pragma unroll
        for (int i = 0; i < 2; i++) {
            int q   = tid + (i << 8);
            int row = q >> 2;
            int kq  = (q & 3) << 2;
            float4 va = *(const float4 *)(x + (size_t)(bm + row) * 2048 + k0 + kq);
            As[kq + 0][row] = va.x; As[kq + 1][row] = va.y;
            As[kq + 2][row] = va.z; As[kq + 3][row] = va.w;
            float4 vb = *(const float4 *)(W + (size_t)(bn + row) * 2048 + k0 + kq);
            Bs[kq + 0][row] = vb.x; Bs[kq + 1][row] = vb.y;
            Bs[kq + 2][row] = vb.z; Bs[kq + 3][row] = vb.w;
        }
        __syncthreads();
#pragma unroll
        for (int k = 0; k < 16; k++) {
            float a[8], bvv[8];
            *(float4 *)(a)     = *(const float4 *)&As[k][tr];
            *(float4 *)(a + 4) = *(const float4 *)&As[k][tr + 4];
            *(float4 *)(bvv)     = *(const float4 *)&Bs[k][tc];
            *(float4 *)(bvv + 4) = *(const float4 *)&Bs[k][tc + 4];
#pragma unroll
            for (int i = 0; i < 8; i++)
#pragma unroll
                for (int j = 0; j < 8; j++) acc[i][j] += a[i] * bvv[j];
        }
        __syncthreads();
    }

    float bj[8];
#pragma unroll
    for (int j = 0; j < 8; j++) bj[j] = __ldg(&bias[bn + tc + j]);
#pragma unroll
    for (int i = 0; i < 8; i++) {
        float4 v0 = make_float4(acc[i][0] + bj[0], acc[i][1] + bj[1],
                                acc[i][2] + bj[2], acc[i][3] + bj[3]);
        float4 v1 = make_float4(acc[i][4] + bj[4], acc[i][5] + bj[5],
                                acc[i][6] + bj[6], acc[i][7] + bj[7]);
        size_t off = (size_t)(bm + tr + i) * 2048 + bn + tc;
        *(float4 *)(C + off)     = v0;
        *(float4 *)(C + off + 4) = v1;
    }
}

// ------------------------------------------------------------------
// Persistent scan (R6 substrate). 148 blocks (1/SM). Warps 0-7 =
// workers, warp 8 = poller polling the single RED counter.
// R13 deltas vs R6: (a) out[] stores AFTER the release-RED,
// (b) tail confined to warp 0 (__syncwarp instead of 2nd bar1) so
// warps 1-7 start the weight preload during tail compute + wait.
// Publishes stay scalar stcg (r0 is not 16B-aligned -> no vector).
// ------------------------------------------------------------------
__global__ __launch_bounds__(TPB, 1) void mgu_scan(
    const float* __restrict__ h0,
    const float* __restrict__ Wfh, const float* __restrict__ bfh,
    const float* __restrict__ Whf, const float* __restrict__ bhf,
    float* __restrict__ out)
{
    extern __shared__ float sW[];
    __shared__ float sPart[MAXR][8];
    __shared__ float sF[MAXR];
    __shared__ float sHold[MAXR];
    __shared__ float sBfh[MAXR];
    __shared__ float sBhf[MAXR];
    __shared__ unsigned sBase;

    const int b   = blockIdx.x;
    const int tid = threadIdx.x;
    const int r0  = (b * Hn) / NBLK;
    const int r1  = ((b + 1) * Hn) / NBLK;
    const int nr  = r1 - r0;               // 13 or 14

    float* sWf = sW;                        // Wfh rows
    float* sWh = sW + nr * Hn;              // Whf rows

    if (tid == 0) sBase = *(volatile unsigned *)&d_base;

    {   // stage weight rows into SMEM (coalesced float4)
        const float4* gf = (const float4 *)(Wfh + (size_t)r0 * Hn);
        const float4* gh = (const float4 *)(Whf + (size_t)r0 * Hn);
        float4* sf4 = (float4 *)sWf;
        float4* sh4 = (float4 *)sWh;
        const int n4 = nr * (Hn / 4);
        for (int i = tid; i < n4; i += TPB) { sf4[i] = gf[i]; sh4[i] = gh[i]; }
    }
    if (tid < nr) {
        sBfh[tid]  = bfh[r0 + tid];
        sBhf[tid]  = bhf[r0 + tid];
        sHold[tid] = h0[r0 + tid];
    }
    for (int i = b * TPB + tid; i < Hn; i += NBLK * TPB) d_hbuf[i] = h0[i];

    __syncthreads();
    const unsigned base = sBase;
    if (tid == 0) red_arrive(&d_count);      // gen 1: weights + h0 published

    // ---------------- poller warp ----------------
    if (tid >= WTH) {
        for (unsigned g = 1; g <= 2u * SEQ; g++) {
            if (tid == WTH) {
                unsigned target = base + g * (unsigned)NBLK;
                while ((int)(ld_acq(&d_count) - target) < 0) { }
            }
            bar2();
        }
        if (b == 0 && tid == WTH)
            *(volatile unsigned *)&d_base = base + 2u * SEQ * (unsigned)NBLK;
        return;
    }

    // ---------------- workers ----------------
    const int lane = tid & 31;
    const int wid  = tid >> 5;
    const int cA   = wid * 128 + lane * 4;          // conflict-free chunk 0
    const int cB   = 1024 + wid * 128 + lane * 4;   // conflict-free chunk 1

    float xf_c = 0.f, xh_c = 0.f;
    if (tid < nr) {
        xf_c = __ldg(&d_XF[r0 + tid]);
        xh_c = __ldg(&d_XH[r0 + tid]);
    }

    float4 wr[MAXR][2];
#pragma unroll
    for (int r = 0; r < MAXR; r++) {                // preload Wfh for t=0
        wr[r][0] = *(const float4 *)(sWf + r * Hn + cA);
        wr[r][1] = *(const float4 *)(sWf + r * Hn + cB);
    }
    bar2();                                          // gen 1 synced: h ready

    for (int t = 0; t < SEQ; t++) {
        // ===== phase A : f = sigmoid(xf + Wfh h + bfh);  g = f*h =====
        float4 hv0 = __ldcg((const float4 *)&d_hbuf[cA]);
        float4 hv1 = __ldcg((const float4 *)&d_hbuf[cB]);

        float acc[MAXR];
#pragma unroll
        for (int r = 0; r < MAXR; r++) {
            acc[r] = wr[r][0].x * hv0.x + wr[r][0].y * hv0.y
                   + wr[r][0].z * hv0.z + wr[r][0].w * hv0.w
                   + wr[r][1].x * hv1.x + wr[r][1].y * hv1.y
                   + wr[r][1].z * hv1.z + wr[r][1].w * hv1.w;
        }
        // paired butterfly reduction: 6 SHFL per 2 rows
#pragma unroll
        for (int p = 0; p < 7; p++) {
            float a = acc[2 * p], c = acc[2 * p + 1];
            a += __shfl_xor_sync(0xffffffffu, a, 16);
            c += __shfl_xor_sync(0xffffffffu, c, 16);
            float m = (lane < 16) ? a : c;
            m += __shfl_xor_sync(0xffffffffu, m, 8);
            m += __shfl_xor_sync(0xffffffffu, m, 4);
            m += __shfl_xor_sync(0xffffffffu, m, 2);
            m += __shfl_xor_sync(0xffffffffu, m, 1);
            if (lane == 0)       sPart[2 * p][wid]     = m;
            else if (lane == 16) sPart[2 * p + 1][wid] = m;
        }
        bar1();
        if (tid < 32) {                              // tail: warp 0 only
            if (tid < nr) {
                float4 p0 = *(const float4 *)&sPart[tid][0];
                float4 p1 = *(const float4 *)&sPart[tid][4];
                float s = (p0.x + p0.y) + (p0.z + p0.w)
                        + (p1.x + p1.y) + (p1.z + p1.w);
                float z = s + sBfh[tid] + xf_c;
                float f = 1.f / (1.f + __expf(-z));
                sF[tid] = f;
                __stcg(&d_gbuf[r0 + tid], f * sHold[tid]);
            }
            __syncwarp();
            if (tid == 0) red_arrive(&d_count);      // gen 2t+2
        }
#pragma unroll
        for (int r = 0; r < MAXR; r++) {             // preload Whf (overlaps tail+wait)
            wr[r][0] = *(const float4 *)(sWh + r * Hn + cA);
            wr[r][1] = *(const float4 *)(sWh + r * Hn + cB);
        }
        bar2();                                      // gen 2t+2 synced: g ready

        // ===== phase B : h_hat = tanh(Whf g + bhf + xh); update =====
        float4 gv0 = __ldcg((const float4 *)&d_gbuf[cA]);
        float4 gv1 = __ldcg((const float4 *)&d_gbuf[cB]);

        float xf_n = 0.f, xh_n = 0.f;                // prefetch next x-projections
        if (tid < nr && t + 1 < SEQ) {
            xf_n = __ldg(&d_XF[(size_t)(t + 1) * Hn + r0 + tid]);
            xh_n = __ldg(&d_XH[(size_t)(t + 1) * Hn + r0 + tid]);
        }

#pragma unroll
        for (int r = 0; r < MAXR; r++) {
            acc[r] = wr[r][0].x * gv0.x + wr[r][0].y * gv0.y
                   + wr[r][0].z * gv0.z + wr[r][0].w * gv0.w
                   + wr[r][1].x * gv1.x + wr[r][1].y * gv1.y
                   + wr[r][1].z * gv1.z + wr[r][1].w * gv1.w;
        }
#pragma unroll
        for (int p = 0; p < 7; p++) {
            float a = acc[2 * p], c = acc[2 * p + 1];
            a += __shfl_xor_sync(0xffffffffu, a, 16);
            c += __shfl_xor_sync(0xffffffffu, c, 16);
            float m = (lane < 16) ? a : c;
            m += __shfl_xor_sync(0xffffffffu, m, 8);
            m += __shfl_xor_sync(0xffffffffu, m, 4);
            m += __shfl_xor_sync(0xffffffffu, m, 2);
            m += __shfl_xor_sync(0xffffffffu, m, 1);
            if (lane == 0)       sPart[2 * p][wid]     = m;
            else if (lane == 16) sPart[2 * p + 1][wid] = m;
        }
        bar1();
        if (tid < 32) {                              // tail: warp 0 only
            float hn = 0.f;
            if (tid < nr) {
                float4 p0 = *(const float4 *)&sPart[tid][0];
                float4 p1 = *(const float4 *)&sPart[tid][4];
                float s = (p0.x + p0.y) + (p0.z + p0.w)
                        + (p1.x + p1.y) + (p1.z + p1.w);
                float z  = s + sBhf[tid] + xh_c;
                float e2 = __expf(2.f * z);
                float hh = 1.f - 2.f / (e2 + 1.f);      // tanh(z)
                float f  = sF[tid];
                float ho = sHold[tid];
                hn = ho + f * (hh - ho);                // (1-f)*h + f*h_hat
                sHold[tid] = hn;
                __stcg(&d_hbuf[r0 + tid], hn);
            }
            __syncwarp();
            if (tid == 0 && t < SEQ - 1) red_arrive(&d_count);   // gen 2t+3
            // out[] stores AFTER the release: off the sync critical path
            if (tid < nr) {
                out[(size_t)t * Hn + r0 + tid] = hn;
                if (t == SEQ - 1) out[(size_t)SEQ * Hn + r0 + tid] = hn;
            }
        }
        if (t < SEQ - 1) {
#pragma unroll
            for (int r = 0; r < MAXR; r++) {         // preload Wfh for next step
                wr[r][0] = *(const float4 *)(sWf + r * Hn + cA);
                wr[r][1] = *(const float4 *)(sWf + r * Hn + cB);
            }
            bar2();                                  // gen 2t+3 synced: h ready
        }
        xf_c = xf_n;
        xh_c = xh_n;
    }
}

// ------------------------------------------------------------------
extern "C" void kernel_launch(void* const* d_in, const int* in_sizes, int n_in,
                              void* d_out, int out_size)
{
    const float* x   = (const float *)d_in[0];
    const float* h0  = (const float *)d_in[1];
    const float* Wfx = (const float *)d_in[2];
    const float* bfx = (const float *)d_in[3];
    const float* Wfh = (const float *)d_in[4];
    const float* bfh = (const float *)d_in[5];
    const float* Whf = (const float *)d_in[6];
    const float* bhf = (const float *)d_in[7];
    const float* Whx = (const float *)d_in[8];
    const float* bhx = (const float *)d_in[9];
    float* out = (float *)d_out;

    (void)in_sizes; (void)n_in; (void)out_size;

    const size_t smem = (size_t)MAXR * Hn * 2 * sizeof(float);  // 229376 B
    cudaFuncSetAttribute(mgu_scan, cudaFuncAttributeMaxDynamicSharedMemorySize,
                         (int)smem);

    mgu_gemm<<<dim3(16, 16, 2), 256>>>(x, Wfx, bfx, Whx, bhx);
    mgu_scan<<<NBLK, TPB, smem>>>(h0, Wfh, bfh, Whf, bhf, out);
}

// round 14
// speedup vs baseline: 1.7929x; 1.0736x over previous
#include <cuda_runtime.h>
#include <math.h>

#define Hn   2048
#define SEQ  2048
#define NBLK 148
#define TPB  288     // 8 worker warps (256) + 1 poller warp
#define WTH  256
#define MAXR 14      // max rows per block: ceil(2048/148)

// ------------------------------------------------------------------
// Static device scratch (no cudaMalloc allowed)
// ------------------------------------------------------------------
__device__ float d_XF[SEQ * Hn];   // x @ Wfx^T + bfx
__device__ float d_XH[SEQ * Hn];   // x @ Whx^T + bhx
__device__ float d_hbuf[Hn];       // hidden state (cross-block)
__device__ float d_gbuf[Hn];       // f * h (cross-block)
__device__ unsigned d_count = 0;   // monotonic barrier arrival counter
__device__ unsigned d_base  = 0;   // counter value at start of this run

__device__ __forceinline__ void red_arrive(unsigned* p) {
    asm volatile("red.release.gpu.global.add.u32 [%0], %1;"
                 :: "l"(p), "r"(1u) : "memory");
}
__device__ __forceinline__ unsigned ld_acq(const unsigned* p) {
    unsigned v;
    asm volatile("ld.acquire.gpu.global.u32 %0, [%1];" : "=r"(v) : "l"(p) : "memory");
    return v;
}
// workers-only barrier
__device__ __forceinline__ void bar1() {
    asm volatile("bar.sync 1, %0;" :: "n"(WTH) : "memory");
}
// workers + poller barrier
__device__ __forceinline__ void bar2() {
    asm volatile("bar.sync 2, %0;" :: "n"(TPB) : "memory");
}

// ------------------------------------------------------------------
// Precompute GEMM:  C[s][n] = sum_k x[s][k] * W[n][k] + bias[n]
// 128x128 tile, BK=16, 8x8/thread, 2-stage double-buffered SMEM:
// next tile's LDGs issue before compute, land in the alternate
// buffer, one __syncthreads per iteration.
// ------------------------------------------------------------------
__global__ __launch_bounds__(256, 2) void mgu_gemm(
    const float* __restrict__ x,
    const float* __restrict__ Wfx, const float* __restrict__ bfx,
    const float* __restrict__ Whx, const float* __restrict__ bhx)
{
    const float* __restrict__ W    = (blockIdx.z == 0) ? Wfx : Whx;
    const float* __restrict__ bias = (blockIdx.z == 0) ? bfx : bhx;
    float* __restrict__ C          = (blockIdx.z == 0) ? d_XF : d_XH;

    __shared__ float As[2][16][132];
    __shared__ float Bs[2][16][132];

    const int bm  = blockIdx.y * 128;
    const int bn  = blockIdx.x * 128;
    const int tid = threadIdx.x;
    const int tr  = (tid >> 4) << 3;
    const int tc  = (tid & 15) << 3;

    // per-thread load slots: i=0,1 -> (row, kq)
    int lrow[2], lkq[2];
#pragma unroll
    for (int i = 0; i < 2; i++) {
        int q   = tid + (i << 8);
        lrow[i] = q >> 2;
        lkq[i]  = (q & 3) << 2;
    }

    float4 va[2], vb[2];
    // prologue: load k-tile 0
#pragma unroll
    for (int i = 0; i < 2; i++) {
        va[i] = *(const float4 *)(x + (size_t)(bm + lrow[i]) * 2048 + lkq[i]);
        vb[i] = *(const float4 *)(W + (size_t)(bn + lrow[i]) * 2048 + lkq[i]);
    }
#pragma unroll
    for (int i = 0; i < 2; i++) {
        As[0][lkq[i] + 0][lrow[i]] = va[i].x; As[0][lkq[i] + 1][lrow[i]] = va[i].y;
        As[0][lkq[i] + 2][lrow[i]] = va[i].z; As[0][lkq[i] + 3][lrow[i]] = va[i].w;
        Bs[0][lkq[i] + 0][lrow[i]] = vb[i].x; Bs[0][lkq[i] + 1][lrow[i]] = vb[i].y;
        Bs[0][lkq[i] + 2][lrow[i]] = vb[i].z; Bs[0][lkq[i] + 3][lrow[i]] = vb[i].w;
    }
    __syncthreads();

    float acc[8][8];
#pragma unroll
    for (int i = 0; i < 8; i++)
#pragma unroll
        for (int j = 0; j < 8; j++) acc[i][j] = 0.f;

    for (int it = 0; it < 128; it++) {
        const int cur = it & 1;
        const int nxt = cur ^ 1;
        const bool more = (it < 127);
        if (more) {                       // issue next tile's loads (in flight)
            int k0 = (it + 1) << 4;
#pragma unroll
            for (int i = 0; i < 2; i++) {
                va[i] = *(const float4 *)(x + (size_t)(bm + lrow[i]) * 2048 + k0 + lkq[i]);
                vb[i] = *(const float4 *)(W + (size_t)(bn + lrow[i]) * 2048 + k0 + lkq[i]);
            }
        }
#pragma unroll
        for (int k = 0; k < 16; k++) {
            float a[8], bvv[8];
            *(float4 *)(a)     = *(const float4 *)&As[cur][k][tr];
            *(float4 *)(a + 4) = *(const float4 *)&As[cur][k][tr + 4];
            *(float4 *)(bvv)     = *(const float4 *)&Bs[cur][k][tc];
            *(float4 *)(bvv + 4) = *(const float4 *)&Bs[cur][k][tc + 4];
#pragma unroll
            for (int i = 0; i < 8; i++)
#pragma unroll
                for (int j = 0; j < 8; j++) acc[i][j] += a[i] * bvv[j];
        }
        if (more) {                       // stage into the alternate buffer
#pragma unroll
            for (int i = 0; i < 2; i++) {
                As[nxt][lkq[i] + 0][lrow[i]] = va[i].x; As[nxt][lkq[i] + 1][lrow[i]] = va[i].y;
                As[nxt][lkq[i] + 2][lrow[i]] = va[i].z; As[nxt][lkq[i] + 3][lrow[i]] = va[i].w;
                Bs[nxt][lkq[i] + 0][lrow[i]] = vb[i].x; Bs[nxt][lkq[i] + 1][lrow[i]] = vb[i].y;
                Bs[nxt][lkq[i] + 2][lrow[i]] = vb[i].z; Bs[nxt][lkq[i] + 3][lrow[i]] = vb[i].w;
            }
            __syncthreads();
        }
    }

    float bj[8];
#pragma unroll
    for (int j = 0; j < 8; j++) bj[j] = __ldg(&bias[bn + tc + j]);
#pragma unroll
    for (int i = 0; i < 8; i++) {
        float4 v0 = make_float4(acc[i][0] + bj[0], acc[i][1] + bj[1],
                                acc[i][2] + bj[2], acc[i][3] + bj[3]);
        float4 v1 = make_float4(acc[i][4] + bj[4], acc[i][5] + bj[5],
                                acc[i][6] + bj[6], acc[i][7] + bj[7]);
        size_t off = (size_t)(bm + tr + i) * 2048 + bn + tc;
        *(float4 *)(C + off)     = v0;
        *(float4 *)(C + off + 4) = v1;
    }
}

// ------------------------------------------------------------------
// Persistent scan: EXACT R6 structure (best measured: 11.07 ms).
// 148 blocks (1/SM). Warps 0-7 = workers, warp 8 = poller polling
// the single RED counter. Weight preloads into registers happen only
// inside barrier windows; second bar1 keeps the SM quiet for the tail.
// ------------------------------------------------------------------
__global__ __launch_bounds__(TPB, 1) void mgu_scan(
    const float* __restrict__ h0,
    const float* __restrict__ Wfh, const float* __restrict__ bfh,
    const float* __restrict__ Whf, const float* __restrict__ bhf,
    float* __restrict__ out)
{
    extern __shared__ float sW[];
    __shared__ float sPart[MAXR][8];
    __shared__ float sF[MAXR];
    __shared__ float sHold[MAXR];
    __shared__ float sBfh[MAXR];
    __shared__ float sBhf[MAXR];
    __shared__ unsigned sBase;

    const int b   = blockIdx.x;
    const int tid = threadIdx.x;
    const int r0  = (b * Hn) / NBLK;
    const int r1  = ((b + 1) * Hn) / NBLK;
    const int nr  = r1 - r0;               // 13 or 14

    float* sWf = sW;                        // Wfh rows
    float* sWh = sW + nr * Hn;              // Whf rows

    if (tid == 0) sBase = *(volatile unsigned *)&d_base;

    {   // stage weight rows into SMEM (coalesced float4)
        const float4* gf = (const float4 *)(Wfh + (size_t)r0 * Hn);
        const float4* gh = (const float4 *)(Whf + (size_t)r0 * Hn);
        float4* sf4 = (float4 *)sWf;
        float4* sh4 = (float4 *)sWh;
        const int n4 = nr * (Hn / 4);
        for (int i = tid; i < n4; i += TPB) { sf4[i] = gf[i]; sh4[i] = gh[i]; }
    }
    if (tid < nr) {
        sBfh[tid]  = bfh[r0 + tid];
        sBhf[tid]  = bhf[r0 + tid];
        sHold[tid] = h0[r0 + tid];
    }
    for (int i = b * TPB + tid; i < Hn; i += NBLK * TPB) d_hbuf[i] = h0[i];

    __syncthreads();
    const unsigned base = sBase;
    if (tid == 0) red_arrive(&d_count);      // gen 1: weights + h0 published

    // ---------------- poller warp ----------------
    if (tid >= WTH) {
        for (unsigned g = 1; g <= 2u * SEQ; g++) {
            if (tid == WTH) {
                unsigned target = base + g * (unsigned)NBLK;
                while ((int)(ld_acq(&d_count) - target) < 0) { }
            }
            bar2();
        }
        if (b == 0 && tid == WTH)
            *(volatile unsigned *)&d_base = base + 2u * SEQ * (unsigned)NBLK;
        return;
    }

    // ---------------- workers ----------------
    const int lane = tid & 31;
    const int wid  = tid >> 5;
    const int cA   = wid * 128 + lane * 4;          // conflict-free chunk 0
    const int cB   = 1024 + wid * 128 + lane * 4;   // conflict-free chunk 1

    float xf_c = 0.f, xh_c = 0.f;
    if (tid < nr) {
        xf_c = __ldg(&d_XF[r0 + tid]);
        xh_c = __ldg(&d_XH[r0 + tid]);
    }

    float4 wr[MAXR][2];
#pragma unroll
    for (int r = 0; r < MAXR; r++) {                // preload Wfh for t=0
        wr[r][0] = *(const float4 *)(sWf + r * Hn + cA);
        wr[r][1] = *(const float4 *)(sWf + r * Hn + cB);
    }
    bar2();                                          // gen 1 synced: h ready

    for (int t = 0; t < SEQ; t++) {
        // ===== phase A : f = sigmoid(xf + Wfh h + bfh);  g = f*h =====
        float4 hv0 = __ldcg((const float4 *)&d_hbuf[cA]);
        float4 hv1 = __ldcg((const float4 *)&d_hbuf[cB]);

        float acc[MAXR];
#pragma unroll
        for (int r = 0; r < MAXR; r++) {
            acc[r] = wr[r][0].x * hv0.x + wr[r][0].y * hv0.y
                   + wr[r][0].z * hv0.z + wr[r][0].w * hv0.w
                   + wr[r][1].x * hv1.x + wr[r][1].y * hv1.y
                   + wr[r][1].z * hv1.z + wr[r][1].w * hv1.w;
        }
        // paired butterfly reduction: 6 SHFL per 2 rows
#pragma unroll
        for (int p = 0; p < 7; p++) {
            float a = acc[2 * p], c = acc[2 * p + 1];
            a += __shfl_xor_sync(0xffffffffu, a, 16);
            c += __shfl_xor_sync(0xffffffffu, c, 16);
            float m = (lane < 16) ? a : c;
            m += __shfl_xor_sync(0xffffffffu, m, 8);
            m += __shfl_xor_sync(0xffffffffu, m, 4);
            m += __shfl_xor_sync(0xffffffffu, m, 2);
            m += __shfl_xor_sync(0xffffffffu, m, 1);
            if (lane == 0)       sPart[2 * p][wid]     = m;
            else if (lane == 16) sPart[2 * p + 1][wid] = m;
        }
        bar1();
        if (tid < nr) {
            float4 p0 = *(const float4 *)&sPart[tid][0];
            float4 p1 = *(const float4 *)&sPart[tid][4];
            float s = (p0.x + p0.y) + (p0.z + p0.w)
                    + (p1.x + p1.y) + (p1.z + p1.w);
            float z = s + sBfh[tid] + xf_c;
            float f = 1.f / (1.f + __expf(-z));
            sF[tid] = f;
            __stcg(&d_gbuf[r0 + tid], f * sHold[tid]);
        }
        bar1();
        if (tid == 0) red_arrive(&d_count);          // gen 2t+2
#pragma unroll
        for (int r = 0; r < MAXR; r++) {             // preload Whf (hidden under sync)
            wr[r][0] = *(const float4 *)(sWh + r * Hn + cA);
            wr[r][1] = *(const float4 *)(sWh + r * Hn + cB);
        }
        bar2();                                      // gen 2t+2 synced: g ready

        // ===== phase B : h_hat = tanh(Whf g + bhf + xh); update =====
        float4 gv0 = __ldcg((const float4 *)&d_gbuf[cA]);
        float4 gv1 = __ldcg((const float4 *)&d_gbuf[cB]);

        float xf_n = 0.f, xh_n = 0.f;                // prefetch next x-projections
        if (tid < nr && t + 1 < SEQ) {
            xf_n = __ldg(&d_XF[(size_t)(t + 1) * Hn + r0 + tid]);
            xh_n = __ldg(&d_XH[(size_t)(t + 1) * Hn + r0 + tid]);
        }

#pragma unroll
        for (int r = 0; r < MAXR; r++) {
            acc[r] = wr[r][0].x * gv0.x + wr[r][0].y * gv0.y
                   + wr[r][0].z * gv0.z + wr[r][0].w * gv0.w
                   + wr[r][1].x * gv1.x + wr[r][1].y * gv1.y
                   + wr[r][1].z * gv1.z + wr[r][1].w * gv1.w;
        }
#pragma unroll
        for (int p = 0; p < 7; p++) {
            float a = acc[2 * p], c = acc[2 * p + 1];
            a += __shfl_xor_sync(0xffffffffu, a, 16);
            c += __shfl_xor_sync(0xffffffffu, c, 16);
            float m = (lane < 16) ? a : c;
            m += __shfl_xor_sync(0xffffffffu, m, 8);
            m += __shfl_xor_sync(0xffffffffu, m, 4);
            m += __shfl_xor_sync(0xffffffffu, m, 2);
            m += __shfl_xor_sync(0xffffffffu, m, 1);
            if (lane == 0)       sPart[2 * p][wid]     = m;
            else if (lane == 16) sPart[2 * p + 1][wid] = m;
        }
        bar1();
        if (tid < nr) {
            float4 p0 = *(const float4 *)&sPart[tid][0];
            float4 p1 = *(const float4 *)&sPart[tid][4];
            float s = (p0.x + p0.y) + (p0.z + p0.w)
                    + (p1.x + p1.y) + (p1.z + p1.w);
            float z  = s + sBhf[tid] + xh_c;
            float e2 = __expf(2.f * z);
            float hh = 1.f - 2.f / (e2 + 1.f);      // tanh(z)
            float f  = sF[tid];
            float ho = sHold[tid];
            float hn = ho + f * (hh - ho);          // (1-f)*h + f*h_hat
            sHold[tid] = hn;
            int row = r0 + tid;
            out[(size_t)t * Hn + row] = hn;
            __stcg(&d_hbuf[row], hn);
            if (t == SEQ - 1) out[(size_t)SEQ * Hn + row] = hn;  // h_final
        }
        bar1();
        if (t < SEQ - 1) {
            if (tid == 0) red_arrive(&d_count);      // gen 2t+3
#pragma unroll
            for (int r = 0; r < MAXR; r++) {         // preload Wfh for next step
                wr[r][0] = *(const float4 *)(sWf + r * Hn + cA);
                wr[r][1] = *(const float4 *)(sWf + r * Hn + cB);
            }
            bar2();                                  // gen 2t+3 synced: h ready
        }
        xf_c = xf_n;
        xh_c = xh_n;
    }
}

// ------------------------------------------------------------------
extern "C" void kernel_launch(void* const* d_in, const int* in_sizes, int n_in,
                              void* d_out, int out_size)
{
    const float* x   = (const float *)d_in[0];
    const float* h0  = (const float *)d_in[1];
    const float* Wfx = (const float *)d_in[2];
    const float* bfx = (const float *)d_in[3];
    const float* Wfh = (const float *)d_in[4];
    const float* bfh = (const float *)d_in[5];
    const float* Whf = (const float *)d_in[6];
    const float* bhf = (const float *)d_in[7];
    const float* Whx = (const float *)d_in[8];
    const float* bhx = (const float *)d_in[9];
    float* out = (float *)d_out;

    (void)in_sizes; (void)n_in; (void)out_size;

    const size_t smem = (size_t)MAXR * Hn * 2 * sizeof(float);  // 229376 B
    cudaFuncSetAttribute(mgu_scan, cudaFuncAttributeMaxDynamicSharedMemorySize,
                         (int)smem);

    mgu_gemm<<<dim3(16, 16, 2), 256>>>(x, Wfx, bfx, Whx, bhx);
    mgu_scan<<<NBLK, TPB, smem>>>(h0, Wfh, bfh, Whf, bhf, out);
}

// round 15
// speedup vs baseline: 1.8050x; 1.0068x over previous
#include <cuda_runtime.h>
#include <math.h>

#define Hn   2048
#define SEQ  2048
#define NBLK 148
#define TPB  288     // 8 worker warps (256) + 1 poller warp
#define WTH  256
#define MAXR 14      // max rows per block: ceil(2048/148)

// ------------------------------------------------------------------
// Static device scratch (no cudaMalloc allowed)
// ------------------------------------------------------------------
__device__ float d_XF[SEQ * Hn];   // x @ Wfx^T + bfx
__device__ float d_XH[SEQ * Hn];   // x @ Whx^T + bhx
__device__ float d_hbuf[Hn];       // hidden state (cross-block)
__device__ float d_gbuf[Hn];       // f * h (cross-block)
__device__ unsigned d_count = 0;   // monotonic barrier arrival counter
__device__ unsigned d_base  = 0;   // counter value at start of this run

__device__ __forceinline__ void red_arrive(unsigned* p) {
    asm volatile("red.release.gpu.global.add.u32 [%0], %1;"
                 :: "l"(p), "r"(1u) : "memory");
}
__device__ __forceinline__ unsigned ld_acq(const unsigned* p) {
    unsigned v;
    asm volatile("ld.acquire.gpu.global.u32 %0, [%1];" : "=r"(v) : "l"(p) : "memory");
    return v;
}
// workers-only barrier
__device__ __forceinline__ void bar1() {
    asm volatile("bar.sync 1, %0;" :: "n"(WTH) : "memory");
}
// workers + poller barrier
__device__ __forceinline__ void bar2() {
    asm volatile("bar.sync 2, %0;" :: "n"(TPB) : "memory");
}

// ------------------------------------------------------------------
// Precompute GEMM:  C[s][n] = sum_k x[s][k] * W[n][k] + bias[n]
// 128x128 tile, BK=16, 8x8/thread with 2x2 QUADRANT mapping:
// rows {ty*4..+3, 64+ty*4..+3}, cols {tx*4..+3, 64+tx*4..+3}.
// Within a warp each LDS.128 phase covers 128 contiguous bytes ->
// conflict-free. Double-buffered SMEM (neutral but harmless).
// ------------------------------------------------------------------
__global__ __launch_bounds__(256, 2) void mgu_gemm(
    const float* __restrict__ x,
    const float* __restrict__ Wfx, const float* __restrict__ bfx,
    const float* __restrict__ Whx, const float* __restrict__ bhx)
{
    const float* __restrict__ W    = (blockIdx.z == 0) ? Wfx : Whx;
    const float* __restrict__ bias = (blockIdx.z == 0) ? bfx : bhx;
    float* __restrict__ C          = (blockIdx.z == 0) ? d_XF : d_XH;

    __shared__ float As[2][16][132];
    __shared__ float Bs[2][16][132];

    const int bm  = blockIdx.y * 128;
    const int bn  = blockIdx.x * 128;
    const int tid = threadIdx.x;
    const int tx  = tid & 15;            // 0..15
    const int ty  = tid >> 4;            // 0..15
    const int ra0 = ty * 4;              // row quadrant 0
    const int ra1 = 64 + ty * 4;         // row quadrant 1
    const int cb0 = tx * 4;              // col quadrant 0
    const int cb1 = 64 + tx * 4;         // col quadrant 1

    // per-thread load slots: i=0,1 -> (row, kq)
    int lrow[2], lkq[2];
#pragma unroll
    for (int i = 0; i < 2; i++) {
        int q   = tid + (i << 8);
        lrow[i] = q >> 2;
        lkq[i]  = (q & 3) << 2;
    }

    float4 va[2], vb[2];
    // prologue: load k-tile 0
#pragma unroll
    for (int i = 0; i < 2; i++) {
        va[i] = *(const float4 *)(x + (size_t)(bm + lrow[i]) * 2048 + lkq[i]);
        vb[i] = *(const float4 *)(W + (size_t)(bn + lrow[i]) * 2048 + lkq[i]);
    }
#pragma unroll
    for (int i = 0; i < 2; i++) {
        As[0][lkq[i] + 0][lrow[i]] = va[i].x; As[0][lkq[i] + 1][lrow[i]] = va[i].y;
        As[0][lkq[i] + 2][lrow[i]] = va[i].z; As[0][lkq[i] + 3][lrow[i]] = va[i].w;
        Bs[0][lkq[i] + 0][lrow[i]] = vb[i].x; Bs[0][lkq[i] + 1][lrow[i]] = vb[i].y;
        Bs[0][lkq[i] + 2][lrow[i]] = vb[i].z; Bs[0][lkq[i] + 3][lrow[i]] = vb[i].w;
    }
    __syncthreads();

    float acc[8][8];
#pragma unroll
    for (int i = 0; i < 8; i++)
#pragma unroll
        for (int j = 0; j < 8; j++) acc[i][j] = 0.f;

    for (int it = 0; it < 128; it++) {
        const int cur = it & 1;
        const int nxt = cur ^ 1;
        const bool more = (it < 127);
        if (more) {                       // issue next tile's loads (in flight)
            int k0 = (it + 1) << 4;
#pragma unroll
            for (int i = 0; i < 2; i++) {
                va[i] = *(const float4 *)(x + (size_t)(bm + lrow[i]) * 2048 + k0 + lkq[i]);
                vb[i] = *(const float4 *)(W + (size_t)(bn + lrow[i]) * 2048 + k0 + lkq[i]);
            }
        }
#pragma unroll
        for (int k = 0; k < 16; k++) {
            float a[8], bvv[8];
            *(float4 *)(a)     = *(const float4 *)&As[cur][k][ra0];   // bcast
            *(float4 *)(a + 4) = *(const float4 *)&As[cur][k][ra1];   // bcast
            *(float4 *)(bvv)     = *(const float4 *)&Bs[cur][k][cb0]; // 128B/phase
            *(float4 *)(bvv + 4) = *(const float4 *)&Bs[cur][k][cb1]; // 128B/phase
#pragma unroll
            for (int i = 0; i < 8; i++)
#pragma unroll
                for (int j = 0; j < 8; j++) acc[i][j] += a[i] * bvv[j];
        }
        if (more) {                       // stage into the alternate buffer
#pragma unroll
            for (int i = 0; i < 2; i++) {
                As[nxt][lkq[i] + 0][lrow[i]] = va[i].x; As[nxt][lkq[i] + 1][lrow[i]] = va[i].y;
                As[nxt][lkq[i] + 2][lrow[i]] = va[i].z; As[nxt][lkq[i] + 3][lrow[i]] = va[i].w;
                Bs[nxt][lkq[i] + 0][lrow[i]] = vb[i].x; Bs[nxt][lkq[i] + 1][lrow[i]] = vb[i].y;
                Bs[nxt][lkq[i] + 2][lrow[i]] = vb[i].z; Bs[nxt][lkq[i] + 3][lrow[i]] = vb[i].w;
            }
            __syncthreads();
        }
    }

    // epilogue: quadrant layout -> two float4 stores per logical row
    float bj[8];
#pragma unroll
    for (int j = 0; j < 4; j++) {
        bj[j]     = __ldg(&bias[bn + cb0 + j]);
        bj[j + 4] = __ldg(&bias[bn + cb1 + j]);
    }
#pragma unroll
    for (int i = 0; i < 8; i++) {
        int row = bm + ((i < 4) ? (ra0 + i) : (ra1 + i - 4));
        float4 v0 = make_float4(acc[i][0] + bj[0], acc[i][1] + bj[1],
                                acc[i][2] + bj[2], acc[i][3] + bj[3]);
        float4 v1 = make_float4(acc[i][4] + bj[4], acc[i][5] + bj[5],
                                acc[i][6] + bj[6], acc[i][7] + bj[7]);
        *(float4 *)(C + (size_t)row * 2048 + bn + cb0) = v0;
        *(float4 *)(C + (size_t)row * 2048 + bn + cb1) = v1;
    }
}

// ------------------------------------------------------------------
// Persistent scan: EXACT R6 structure (best measured: 11.07 ms).
// 148 blocks (1/SM). Warps 0-7 = workers, warp 8 = poller polling
// the single RED counter. Weight preloads into registers happen only
// inside barrier windows; second bar1 keeps the SM quiet for the tail.
// ------------------------------------------------------------------
__global__ __launch_bounds__(TPB, 1) void mgu_scan(
    const float* __restrict__ h0,
    const float* __restrict__ Wfh, const float* __restrict__ bfh,
    const float* __restrict__ Whf, const float* __restrict__ bhf,
    float* __restrict__ out)
{
    extern __shared__ float sW[];
    __shared__ float sPart[MAXR][8];
    __shared__ float sF[MAXR];
    __shared__ float sHold[MAXR];
    __shared__ float sBfh[MAXR];
    __shared__ float sBhf[MAXR];
    __shared__ unsigned sBase;

    const int b   = blockIdx.x;
    const int tid = threadIdx.x;
    const int r0  = (b * Hn) / NBLK;
    const int r1  = ((b + 1) * Hn) / NBLK;
    const int nr  = r1 - r0;               // 13 or 14

    float* sWf = sW;                        // Wfh rows
    float* sWh = sW + nr * Hn;              // Whf rows

    if (tid == 0) sBase = *(volatile unsigned *)&d_base;

    {   // stage weight rows into SMEM (coalesced float4)
        const float4* gf = (const float4 *)(Wfh + (size_t)r0 * Hn);
        const float4* gh = (const float4 *)(Whf + (size_t)r0 * Hn);
        float4* sf4 = (float4 *)sWf;
        float4* sh4 = (float4 *)sWh;
        const int n4 = nr * (Hn / 4);
        for (int i = tid; i < n4; i += TPB) { sf4[i] = gf[i]; sh4[i] = gh[i]; }
    }
    if (tid < nr) {
        sBfh[tid]  = bfh[r0 + tid];
        sBhf[tid]  = bhf[r0 + tid];
        sHold[tid] = h0[r0 + tid];
    }
    for (int i = b * TPB + tid; i < Hn; i += NBLK * TPB) d_hbuf[i] = h0[i];

    __syncthreads();
    const unsigned base = sBase;
    if (tid == 0) red_arrive(&d_count);      // gen 1: weights + h0 published

    // ---------------- poller warp ----------------
    if (tid >= WTH) {
        for (unsigned g = 1; g <= 2u * SEQ; g++) {
            if (tid == WTH) {
                unsigned target = base + g * (unsigned)NBLK;
                while ((int)(ld_acq(&d_count) - target) < 0) { }
            }
            bar2();
        }
        if (b == 0 && tid == WTH)
            *(volatile unsigned *)&d_base = base + 2u * SEQ * (unsigned)NBLK;
        return;
    }

    // ---------------- workers ----------------
    const int lane = tid & 31;
    const int wid  = tid >> 5;
    const int cA   = wid * 128 + lane * 4;          // conflict-free chunk 0
    const int cB   = 1024 + wid * 128 + lane * 4;   // conflict-free chunk 1

    float xf_c = 0.f, xh_c = 0.f;
    if (tid < nr) {
        xf_c = __ldg(&d_XF[r0 + tid]);
        xh_c = __ldg(&d_XH[r0 + tid]);
    }

    float4 wr[MAXR][2];
#pragma unroll
    for (int r = 0; r < MAXR; r++) {                // preload Wfh for t=0
        wr[r][0] = *(const float4 *)(sWf + r * Hn + cA);
        wr[r][1] = *(const float4 *)(sWf + r * Hn + cB);
    }
    bar2();                                          // gen 1 synced: h ready

    for (int t = 0; t < SEQ; t++) {
        // ===== phase A : f = sigmoid(xf + Wfh h + bfh);  g = f*h =====
        float4 hv0 = __ldcg((const float4 *)&d_hbuf[cA]);
        float4 hv1 = __ldcg((const float4 *)&d_hbuf[cB]);

        float acc[MAXR];
#pragma unroll
        for (int r = 0; r < MAXR; r++) {
            acc[r] = wr[r][0].x * hv0.x + wr[r][0].y * hv0.y
                   + wr[r][0].z * hv0.z + wr[r][0].w * hv0.w
                   + wr[r][1].x * hv1.x + wr[r][1].y * hv1.y
                   + wr[r][1].z * hv1.z + wr[r][1].w * hv1.w;
        }
        // paired butterfly reduction: 6 SHFL per 2 rows
#pragma unroll
        for (int p = 0; p < 7; p++) {
            float a = acc[2 * p], c = acc[2 * p + 1];
            a += __shfl_xor_sync(0xffffffffu, a, 16);
            c += __shfl_xor_sync(0xffffffffu, c, 16);
            float m = (lane < 16) ? a : c;
            m += __shfl_xor_sync(0xffffffffu, m, 8);
            m += __shfl_xor_sync(0xffffffffu, m, 4);
            m += __shfl_xor_sync(0xffffffffu, m, 2);
            m += __shfl_xor_sync(0xffffffffu, m, 1);
            if (lane == 0)       sPart[2 * p][wid]     = m;
            else if (lane == 16) sPart[2 * p + 1][wid] = m;
        }
        bar1();
        if (tid < nr) {
            float4 p0 = *(const float4 *)&sPart[tid][0];
            float4 p1 = *(const float4 *)&sPart[tid][4];
            float s = (p0.x + p0.y) + (p0.z + p0.w)
                    + (p1.x + p1.y) + (p1.z + p1.w);
            float z = s + sBfh[tid] + xf_c;
            float f = 1.f / (1.f + __expf(-z));
            sF[tid] = f;
            __stcg(&d_gbuf[r0 + tid], f * sHold[tid]);
        }
        bar1();
        if (tid == 0) red_arrive(&d_count);          // gen 2t+2
#pragma unroll
        for (int r = 0; r < MAXR; r++) {             // preload Whf (hidden under sync)
            wr[r][0] = *(const float4 *)(sWh + r * Hn + cA);
            wr[r][1] = *(const float4 *)(sWh + r * Hn + cB);
        }
        bar2();                                      // gen 2t+2 synced: g ready

        // ===== phase B : h_hat = tanh(Whf g + bhf + xh); update =====
        float4 gv0 = __ldcg((const float4 *)&d_gbuf[cA]);
        float4 gv1 = __ldcg((const float4 *)&d_gbuf[cB]);

        float xf_n = 0.f, xh_n = 0.f;                // prefetch next x-projections
        if (tid < nr && t + 1 < SEQ) {
            xf_n = __ldg(&d_XF[(size_t)(t + 1) * Hn + r0 + tid]);
            xh_n = __ldg(&d_XH[(size_t)(t + 1) * Hn + r0 + tid]);
        }

#pragma unroll
        for (int r = 0; r < MAXR; r++) {
            acc[r] = wr[r][0].x * gv0.x + wr[r][0].y * gv0.y
                   + wr[r][0].z * gv0.z + wr[r][0].w * gv0.w
                   + wr[r][1].x * gv1.x + wr[r][1].y * gv1.y
                   + wr[r][1].z * gv1.z + wr[r][1].w * gv1.w;
        }
#pragma unroll
        for (int p = 0; p < 7; p++) {
            float a = acc[2 * p], c = acc[2 * p + 1];
            a += __shfl_xor_sync(0xffffffffu, a, 16);
            c += __shfl_xor_sync(0xffffffffu, c, 16);
            float m = (lane < 16) ? a : c;
            m += __shfl_xor_sync(0xffffffffu, m, 8);
            m += __shfl_xor_sync(0xffffffffu, m, 4);
            m += __shfl_xor_sync(0xffffffffu, m, 2);
            m += __shfl_xor_sync(0xffffffffu, m, 1);
            if (lane == 0)       sPart[2 * p][wid]     = m;
            else if (lane == 16) sPart[2 * p + 1][wid] = m;
        }
        bar1();
        if (tid < nr) {
            float4 p0 = *(const float4 *)&sPart[tid][0];
            float4 p1 = *(const float4 *)&sPart[tid][4];
            float s = (p0.x + p0.y) + (p0.z + p0.w)
                    + (p1.x + p1.y) + (p1.z + p1.w);
            float z  = s + sBhf[tid] + xh_c;
            float e2 = __expf(2.f * z);
            float hh = 1.f - 2.f / (e2 + 1.f);      // tanh(z)
            float f  = sF[tid];
            float ho = sHold[tid];
            float hn = ho + f * (hh - ho);          // (1-f)*h + f*h_hat
            sHold[tid] = hn;
            int row = r0 + tid;
            out[(size_t)t * Hn + row] = hn;
            __stcg(&d_hbuf[row], hn);
            if (t == SEQ - 1) out[(size_t)SEQ * Hn + row] = hn;  // h_final
        }
        bar1();
        if (t < SEQ - 1) {
            if (tid == 0) red_arrive(&d_count);      // gen 2t+3
#pragma unroll
            for (int r = 0; r < MAXR; r++) {         // preload Wfh for next step
                wr[r][0] = *(const float4 *)(sWf + r * Hn + cA);
                wr[r][1] = *(const float4 *)(sWf + r * Hn + cB);
            }
            bar2();                                  // gen 2t+3 synced: h ready
        }
        xf_c = xf_n;
        xh_c = xh_n;
    }
}

// ------------------------------------------------------------------
extern "C" void kernel_launch(void* const* d_in, const int* in_sizes, int n_in,
                              void* d_out, int out_size)
{
    const float* x   = (const float *)d_in[0];
    const float* h0  = (const float *)d_in[1];
    const float* Wfx = (const float *)d_in[2];
    const float* bfx = (const float *)d_in[3];
    const float* Wfh = (const float *)d_in[4];
    const float* bfh = (const float *)d_in[5];
    const float* Whf = (const float *)d_in[6];
    const float* bhf = (const float *)d_in[7];
    const float* Whx = (const float *)d_in[8];
    const float* bhx = (const float *)d_in[9];
    float* out = (float *)d_out;

    (void)in_sizes; (void)n_in; (void)out_size;

    const size_t smem = (size_t)MAXR * Hn * 2 * sizeof(float);  // 229376 B
    cudaFuncSetAttribute(mgu_scan, cudaFuncAttributeMaxDynamicSharedMemorySize,
                         (int)smem);

    mgu_gemm<<<dim3(16, 16, 2), 256>>>(x, Wfx, bfx, Whx, bhx);
    mgu_scan<<<NBLK, TPB, smem>>>(h0, Wfh, bfh, Whf, bhf, out);
}

// round 16
// speedup vs baseline: 1.8129x; 1.0044x over previous
#include <cuda_runtime.h>
#include <math.h>

#define Hn   2048
#define SEQ  2048
#define NBLK 148
#define TPB  288     // 8 worker warps (256) + 1 poller warp
#define WTH  256
#define MAXR 14      // max rows per block: ceil(2048/148)
#define NREP 4       // replicas of the exchange vectors (LTS spread)

// ------------------------------------------------------------------
// Static device scratch (no cudaMalloc allowed)
// ------------------------------------------------------------------
__device__ float d_XF[SEQ * Hn];        // x @ Wfx^T + bfx
__device__ float d_XH[SEQ * Hn];        // x @ Whx^T + bhx
__device__ float d_hbuf[NREP][Hn];      // hidden state, 4 replicas
__device__ float d_gbuf[NREP][Hn];      // f * h, 4 replicas
__device__ unsigned d_count = 0;        // monotonic barrier arrival counter
__device__ unsigned d_base  = 0;        // counter value at start of this run

__device__ __forceinline__ void red_arrive(unsigned* p) {
    asm volatile("red.release.gpu.global.add.u32 [%0], %1;"
                 :: "l"(p), "r"(1u) : "memory");
}
__device__ __forceinline__ unsigned ld_acq(const unsigned* p) {
    unsigned v;
    asm volatile("ld.acquire.gpu.global.u32 %0, [%1];" : "=r"(v) : "l"(p) : "memory");
    return v;
}
// workers-only barrier
__device__ __forceinline__ void bar1() {
    asm volatile("bar.sync 1, %0;" :: "n"(WTH) : "memory");
}
// workers + poller barrier
__device__ __forceinline__ void bar2() {
    asm volatile("bar.sync 2, %0;" :: "n"(TPB) : "memory");
}

// ------------------------------------------------------------------
// Precompute GEMM:  C[s][n] = sum_k x[s][k] * W[n][k] + bias[n]
// 128x128 tile, BK=16, 8x8/thread, 2x2 quadrant mapping (conflict-
// free LDS), double-buffered SMEM.
// ------------------------------------------------------------------
__global__ __launch_bounds__(256, 2) void mgu_gemm(
    const float* __restrict__ x,
    const float* __restrict__ Wfx, const float* __restrict__ bfx,
    const float* __restrict__ Whx, const float* __restrict__ bhx)
{
    const float* __restrict__ W    = (blockIdx.z == 0) ? Wfx : Whx;
    const float* __restrict__ bias = (blockIdx.z == 0) ? bfx : bhx;
    float* __restrict__ C          = (blockIdx.z == 0) ? d_XF : d_XH;

    __shared__ float As[2][16][132];
    __shared__ float Bs[2][16][132];

    const int bm  = blockIdx.y * 128;
    const int bn  = blockIdx.x * 128;
    const int tid = threadIdx.x;
    const int tx  = tid & 15;
    const int ty  = tid >> 4;
    const int ra0 = ty * 4;
    const int ra1 = 64 + ty * 4;
    const int cb0 = tx * 4;
    const int cb1 = 64 + tx * 4;

    int lrow[2], lkq[2];
#pragma unroll
    for (int i = 0; i < 2; i++) {
        int q   = tid + (i << 8);
        lrow[i] = q >> 2;
        lkq[i]  = (q & 3) << 2;
    }

    float4 va[2], vb[2];
#pragma unroll
    for (int i = 0; i < 2; i++) {
        va[i] = *(const float4 *)(x + (size_t)(bm + lrow[i]) * 2048 + lkq[i]);
        vb[i] = *(const float4 *)(W + (size_t)(bn + lrow[i]) * 2048 + lkq[i]);
    }
#pragma unroll
    for (int i = 0; i < 2; i++) {
        As[0][lkq[i] + 0][lrow[i]] = va[i].x; As[0][lkq[i] + 1][lrow[i]] = va[i].y;
        As[0][lkq[i] + 2][lrow[i]] = va[i].z; As[0][lkq[i] + 3][lrow[i]] = va[i].w;
        Bs[0][lkq[i] + 0][lrow[i]] = vb[i].x; Bs[0][lkq[i] + 1][lrow[i]] = vb[i].y;
        Bs[0][lkq[i] + 2][lrow[i]] = vb[i].z; Bs[0][lkq[i] + 3][lrow[i]] = vb[i].w;
    }
    __syncthreads();

    float acc[8][8];
#pragma unroll
    for (int i = 0; i < 8; i++)
#pragma unroll
        for (int j = 0; j < 8; j++) acc[i][j] = 0.f;

    for (int it = 0; it < 128; it++) {
        const int cur = it & 1;
        const int nxt = cur ^ 1;
        const bool more = (it < 127);
        if (more) {
            int k0 = (it + 1) << 4;
#pragma unroll
            for (int i = 0; i < 2; i++) {
                va[i] = *(const float4 *)(x + (size_t)(bm + lrow[i]) * 2048 + k0 + lkq[i]);
                vb[i] = *(const float4 *)(W + (size_t)(bn + lrow[i]) * 2048 + k0 + lkq[i]);
            }
        }
#pragma unroll
        for (int k = 0; k < 16; k++) {
            float a[8], bvv[8];
            *(float4 *)(a)     = *(const float4 *)&As[cur][k][ra0];
            *(float4 *)(a + 4) = *(const float4 *)&As[cur][k][ra1];
            *(float4 *)(bvv)     = *(const float4 *)&Bs[cur][k][cb0];
            *(float4 *)(bvv + 4) = *(const float4 *)&Bs[cur][k][cb1];
#pragma unroll
            for (int i = 0; i < 8; i++)
#pragma unroll
                for (int j = 0; j < 8; j++) acc[i][j] += a[i] * bvv[j];
        }
        if (more) {
#pragma unroll
            for (int i = 0; i < 2; i++) {
                As[nxt][lkq[i] + 0][lrow[i]] = va[i].x; As[nxt][lkq[i] + 1][lrow[i]] = va[i].y;
                As[nxt][lkq[i] + 2][lrow[i]] = va[i].z; As[nxt][lkq[i] + 3][lrow[i]] = va[i].w;
                Bs[nxt][lkq[i] + 0][lrow[i]] = vb[i].x; Bs[nxt][lkq[i] + 1][lrow[i]] = vb[i].y;
                Bs[nxt][lkq[i] + 2][lrow[i]] = vb[i].z; Bs[nxt][lkq[i] + 3][lrow[i]] = vb[i].w;
            }
            __syncthreads();
        }
    }

    float bj[8];
#pragma unroll
    for (int j = 0; j < 4; j++) {
        bj[j]     = __ldg(&bias[bn + cb0 + j]);
        bj[j + 4] = __ldg(&bias[bn + cb1 + j]);
    }
#pragma unroll
    for (int i = 0; i < 8; i++) {
        int row = bm + ((i < 4) ? (ra0 + i) : (ra1 + i - 4));
        float4 v0 = make_float4(acc[i][0] + bj[0], acc[i][1] + bj[1],
                                acc[i][2] + bj[2], acc[i][3] + bj[3]);
        float4 v1 = make_float4(acc[i][4] + bj[4], acc[i][5] + bj[5],
                                acc[i][6] + bj[6], acc[i][7] + bj[7]);
        *(float4 *)(C + (size_t)row * 2048 + bn + cb0) = v0;
        *(float4 *)(C + (size_t)row * 2048 + bn + cb1) = v1;
    }
}

// ------------------------------------------------------------------
// Persistent scan: R6 substrate + 4x-replicated exchange vectors.
// Publishers write all replicas (extra stores, off the critical
// path); block b reads replica (b & 3) -> per-LTS-slice gather
// demand drops 4x.
// ------------------------------------------------------------------
__global__ __launch_bounds__(TPB, 1) void mgu_scan(
    const float* __restrict__ h0,
    const float* __restrict__ Wfh, const float* __restrict__ bfh,
    const float* __restrict__ Whf, const float* __restrict__ bhf,
    float* __restrict__ out)
{
    extern __shared__ float sW[];
    __shared__ float sPart[MAXR][8];
    __shared__ float sF[MAXR];
    __shared__ float sHold[MAXR];
    __shared__ float sBfh[MAXR];
    __shared__ float sBhf[MAXR];
    __shared__ unsigned sBase;

    const int b   = blockIdx.x;
    const int tid = threadIdx.x;
    const int r0  = (b * Hn) / NBLK;
    const int r1  = ((b + 1) * Hn) / NBLK;
    const int nr  = r1 - r0;               // 13 or 14

    float* sWf = sW;                        // Wfh rows
    float* sWh = sW + nr * Hn;              // Whf rows

    if (tid == 0) sBase = *(volatile unsigned *)&d_base;

    {   // stage weight rows into SMEM (coalesced float4)
        const float4* gf = (const float4 *)(Wfh + (size_t)r0 * Hn);
        const float4* gh = (const float4 *)(Whf + (size_t)r0 * Hn);
        float4* sf4 = (float4 *)sWf;
        float4* sh4 = (float4 *)sWh;
        const int n4 = nr * (Hn / 4);
        for (int i = tid; i < n4; i += TPB) { sf4[i] = gf[i]; sh4[i] = gh[i]; }
    }
    if (tid < nr) {
        sBfh[tid]  = bfh[r0 + tid];
        sBhf[tid]  = bhf[r0 + tid];
        sHold[tid] = h0[r0 + tid];
    }
    for (int i = b * TPB + tid; i < Hn; i += NBLK * TPB) {
        float v = h0[i];
#pragma unroll
        for (int c = 0; c < NREP; c++) d_hbuf[c][i] = v;
    }

    __syncthreads();
    const unsigned base = sBase;
    if (tid == 0) red_arrive(&d_count);      // gen 1: weights + h0 published

    // ---------------- poller warp ----------------
    if (tid >= WTH) {
        for (unsigned g = 1; g <= 2u * SEQ; g++) {
            if (tid == WTH) {
                unsigned target = base + g * (unsigned)NBLK;
                while ((int)(ld_acq(&d_count) - target) < 0) { }
            }
            bar2();
        }
        if (b == 0 && tid == WTH)
            *(volatile unsigned *)&d_base = base + 2u * SEQ * (unsigned)NBLK;
        return;
    }

    // ---------------- workers ----------------
    const int lane = tid & 31;
    const int wid  = tid >> 5;
    const int cA   = wid * 128 + lane * 4;          // conflict-free chunk 0
    const int cB   = 1024 + wid * 128 + lane * 4;   // conflict-free chunk 1
    const int rep  = b & (NREP - 1);                // this block's read replica
    const float* hb = d_hbuf[rep];
    const float* gb = d_gbuf[rep];

    float xf_c = 0.f, xh_c = 0.f;
    if (tid < nr) {
        xf_c = __ldg(&d_XF[r0 + tid]);
        xh_c = __ldg(&d_XH[r0 + tid]);
    }

    float4 wr[MAXR][2];
#pragma unroll
    for (int r = 0; r < MAXR; r++) {                // preload Wfh for t=0
        wr[r][0] = *(const float4 *)(sWf + r * Hn + cA);
        wr[r][1] = *(const float4 *)(sWf + r * Hn + cB);
    }
    bar2();                                          // gen 1 synced: h ready

    for (int t = 0; t < SEQ; t++) {
        // ===== phase A : f = sigmoid(xf + Wfh h + bfh);  g = f*h =====
        float4 hv0 = __ldcg((const float4 *)&hb[cA]);
        float4 hv1 = __ldcg((const float4 *)&hb[cB]);

        float acc[MAXR];
#pragma unroll
        for (int r = 0; r < MAXR; r++) {
            acc[r] = wr[r][0].x * hv0.x + wr[r][0].y * hv0.y
                   + wr[r][0].z * hv0.z + wr[r][0].w * hv0.w
                   + wr[r][1].x * hv1.x + wr[r][1].y * hv1.y
                   + wr[r][1].z * hv1.z + wr[r][1].w * hv1.w;
        }
        // paired butterfly reduction: 6 SHFL per 2 rows
#pragma unroll
        for (int p = 0; p < 7; p++) {
            float a = acc[2 * p], c = acc[2 * p + 1];
            a += __shfl_xor_sync(0xffffffffu, a, 16);
            c += __shfl_xor_sync(0xffffffffu, c, 16);
            float m = (lane < 16) ? a : c;
            m += __shfl_xor_sync(0xffffffffu, m, 8);
            m += __shfl_xor_sync(0xffffffffu, m, 4);
            m += __shfl_xor_sync(0xffffffffu, m, 2);
            m += __shfl_xor_sync(0xffffffffu, m, 1);
            if (lane == 0)       sPart[2 * p][wid]     = m;
            else if (lane == 16) sPart[2 * p + 1][wid] = m;
        }
        bar1();
        if (tid < nr) {
            float4 p0 = *(const float4 *)&sPart[tid][0];
            float4 p1 = *(const float4 *)&sPart[tid][4];
            float s = (p0.x + p0.y) + (p0.z + p0.w)
                    + (p1.x + p1.y) + (p1.z + p1.w);
            float z = s + sBfh[tid] + xf_c;
            float f = 1.f / (1.f + __expf(-z));
            sF[tid] = f;
            float gv = f * sHold[tid];
            int row = r0 + tid;
#pragma unroll
            for (int c = 0; c < NREP; c++) __stcg(&d_gbuf[c][row], gv);
        }
        bar1();
        if (tid == 0) red_arrive(&d_count);          // gen 2t+2
#pragma unroll
        for (int r = 0; r < MAXR; r++) {             // preload Whf (hidden under sync)
            wr[r][0] = *(const float4 *)(sWh + r * Hn + cA);
            wr[r][1] = *(const float4 *)(sWh + r * Hn + cB);
        }
        bar2();                                      // gen 2t+2 synced: g ready

        // ===== phase B : h_hat = tanh(Whf g + bhf + xh); update =====
        float4 gv0 = __ldcg((const float4 *)&gb[cA]);
        float4 gv1 = __ldcg((const float4 *)&gb[cB]);

        float xf_n = 0.f, xh_n = 0.f;                // prefetch next x-projections
        if (tid < nr && t + 1 < SEQ) {
            xf_n = __ldg(&d_XF[(size_t)(t + 1) * Hn + r0 + tid]);
            xh_n = __ldg(&d_XH[(size_t)(t + 1) * Hn + r0 + tid]);
        }

#pragma unroll
        for (int r = 0; r < MAXR; r++) {
            acc[r] = wr[r][0].x * gv0.x + wr[r][0].y * gv0.y
                   + wr[r][0].z * gv0.z + wr[r][0].w * gv0.w
                   + wr[r][1].x * gv1.x + wr[r][1].y * gv1.y
                   + wr[r][1].z * gv1.z + wr[r][1].w * gv1.w;
        }
#pragma unroll
        for (int p = 0; p < 7; p++) {
            float a = acc[2 * p], c = acc[2 * p + 1];
            a += __shfl_xor_sync(0xffffffffu, a, 16);
            c += __shfl_xor_sync(0xffffffffu, c, 16);
            float m = (lane < 16) ? a : c;
            m += __shfl_xor_sync(0xffffffffu, m, 8);
            m += __shfl_xor_sync(0xffffffffu, m, 4);
            m += __shfl_xor_sync(0xffffffffu, m, 2);
            m += __shfl_xor_sync(0xffffffffu, m, 1);
            if (lane == 0)       sPart[2 * p][wid]     = m;
            else if (lane == 16) sPart[2 * p + 1][wid] = m;
        }
        bar1();
        if (tid < nr) {
            float4 p0 = *(const float4 *)&sPart[tid][0];
            float4 p1 = *(const float4 *)&sPart[tid][4];
            float s = (p0.x + p0.y) + (p0.z + p0.w)
                    + (p1.x + p1.y) + (p1.z + p1.w);
            float z  = s + sBhf[tid] + xh_c;
            float e2 = __expf(2.f * z);
            float hh = 1.f - 2.f / (e2 + 1.f);      // tanh(z)
            float f  = sF[tid];
            float ho = sHold[tid];
            float hn = ho + f * (hh - ho);          // (1-f)*h + f*h_hat
            sHold[tid] = hn;
            int row = r0 + tid;
            out[(size_t)t * Hn + row] = hn;
#pragma unroll
            for (int c = 0; c < NREP; c++) __stcg(&d_hbuf[c][row], hn);
            if (t == SEQ - 1) out[(size_t)SEQ * Hn + row] = hn;  // h_final
        }
        bar1();
        if (t < SEQ - 1) {
            if (tid == 0) red_arrive(&d_count);      // gen 2t+3
#pragma unroll
            for (int r = 0; r < MAXR; r++) {         // preload Wfh for next step
                wr[r][0] = *(const float4 *)(sWf + r * Hn + cA);
                wr[r][1] = *(const float4 *)(sWf + r * Hn + cB);
            }
            bar2();                                  // gen 2t+3 synced: h ready
        }
        xf_c = xf_n;
        xh_c = xh_n;
    }
}

// ------------------------------------------------------------------
extern "C" void kernel_launch(void* const* d_in, const int* in_sizes, int n_in,
                              void* d_out, int out_size)
{
    const float* x   = (const float *)d_in[0];
    const float* h0  = (const float *)d_in[1];
    const float* Wfx = (const float *)d_in[2];
    const float* bfx = (const float *)d_in[3];
    const float* Wfh = (const float *)d_in[4];
    const float* bfh = (const float *)d_in[5];
    const float* Whf = (const float *)d_in[6];
    const float* bhf = (const float *)d_in[7];
    const float* Whx = (const float *)d_in[8];
    const float* bhx = (const float *)d_in[9];
    float* out = (float *)d_out;

    (void)in_sizes; (void)n_in; (void)out_size;

    const size_t smem = (size_t)MAXR * Hn * 2 * sizeof(float);  // 229376 B
    cudaFuncSetAttribute(mgu_scan, cudaFuncAttributeMaxDynamicSharedMemorySize,
                         (int)smem);

    mgu_gemm<<<dim3(16, 16, 2), 256>>>(x, Wfx, bfx, Whx, bhx);
    mgu_scan<<<NBLK, TPB, smem>>>(h0, Wfh, bfh, Whf, bhf, out);
}